// round 9
// baseline (speedup 1.0000x reference)
#include <cuda_runtime.h>
#include <cstdint>

#define THREADS 1024
#define IN_DIM  2304
#define OUT_DIM 576
#define BATCH   16384
#define RS4     704                 // padded row stride in float4
#define CHUNK   8                   // rows per chunk
#define NCTA    148
#define XBUF_F4 (CHUNK * RS4)       // 5632 float4 per buffer
#define SMEM_BYTES (2 * XBUF_F4 * 16)   // 180224

// Padded smem row layout (float4 indices within one x row):
//   seg1: 16 groups, stride 4  -> [0, 64)      (warp: 16 f4 -> 2 wavefronts)
//   seg2: 32 groups, stride 12 -> [64, 448)    (12 % 8 == 4: two groups per
//                                               warp on disjoint bank quads)
//   seg3: 16 groups, stride 16 -> [448, 704)   (one group/warp, 4 f4 = 64B)
__device__ __forceinline__ int pad_map(int f) {
    if (f < 64)  return f;
    if (f < 320) return 64 + (f - 64) + (((f - 64) >> 3) << 2);
    return 448 + (f - 320);
}

__device__ __forceinline__ void cpa16(uint32_t daddr, const void* src) {
    asm volatile("cp.async.cg.shared.global [%0], [%1], 16;\n" :: "r"(daddr), "l"(src));
}

// packed f32x2 helpers
#define FMA2(acc, a, b) \
    asm("fma.rn.f32x2 %0, %1, %2, %0;" : "+l"(acc) : "l"(a), "l"(b))
#define PACK2(p, lo, hi) \
    asm("mov.b64 %0, {%1, %2};" : "=l"(p) : "f"(lo), "f"(hi))
#define LDS_V2B64(lo, hi, addr) \
    asm("ld.shared.v2.b64 {%0, %1}, [%2];" : "=l"(lo), "=l"(hi) : "r"(addr))

__device__ __forceinline__ float hsum2(uint64_t p) {
    float lo, hi;
    asm("mov.b64 {%0, %1}, %2;" : "=f"(lo), "=f"(hi) : "l"(p));
    return lo + hi;
}

extern "C" __global__ void __launch_bounds__(THREADS, 1)
tet_kernel(const float* __restrict__ x, const float* __restrict__ w,
           const float* __restrict__ bias, float* __restrict__ out)
{
    extern __shared__ __align__(16) float4 Xs[];          // [2][CHUNK][RS4]

    const int tid = threadIdx.x;
    const int bid = blockIdx.x;

    // row partition: 16384 = 148*110 + 104
    const int row0  = bid * 110 + (bid < 104 ? bid : 104);
    const int nrows = 110 + (bid < 104 ? 1 : 0);
    const int nchunks = (nrows + CHUNK - 1) / CHUNK;      // 14

    const int h = tid & 3;          // K-quarter (4 lanes per column pair)

    // ---- role setup ----
    // Quarter h owns f4 indices {4*k4 + h} of its group, i.e. k = 16*k4+4*h+(0..3).
    uint64_t wA2[8], wB2[8];        // seg3: 8 each; seg2: 4 each
    uint64_t wC2[2], wD2[2];        // overlay seg1 (4 warps of seg2)
    int xoff, colMain;
    int xoff1 = 0, colOvl = 0;
    bool ovl = false;
    int N4;

    if (tid < 512) {                // seg3: 16 groups x 16 cols, N4 = 4
        const int q = tid >> 2, g3 = q >> 3, cp3 = q & 7;
        const int base = 9216 + g3 * 1024;
        #pragma unroll
        for (int k4 = 0; k4 < 4; k4++)
            #pragma unroll
            for (int j = 0; j < 2; j++) {
                int k = 16 * k4 + 4 * h + 2 * j;
                PACK2(wA2[2*k4+j], w[base + k * 16 + cp3],     w[base + (k+1) * 16 + cp3]);
                PACK2(wB2[2*k4+j], w[base + k * 16 + cp3 + 8], w[base + (k+1) * 16 + cp3 + 8]);
            }
        xoff = 448 + 16 * g3;
        const int colA = 320 + 16 * g3 + cp3;
        colMain = (h & 1) ? colA + 8 : colA;
        N4 = 4;
    } else {                        // seg2: 32 groups x 8 cols, N4 = 2
        const int p = tid - 512, q = p >> 2, g2 = q >> 2, cp2 = q & 3;
        const int base = 1024 + g2 * 256;
        #pragma unroll
        for (int k4 = 0; k4 < 2; k4++)
            #pragma unroll
            for (int j = 0; j < 2; j++) {
                int k = 16 * k4 + 4 * h + 2 * j;
                PACK2(wA2[2*k4+j], w[base + k * 8 + cp2],     w[base + (k+1) * 8 + cp2]);
                PACK2(wB2[2*k4+j], w[base + k * 8 + cp2 + 4], w[base + (k+1) * 8 + cp2 + 4]);
            }
        xoff = 64 + 12 * g2;
        const int colA = 64 + 8 * g2 + cp2;
        colMain = (h & 1) ? colA + 4 : colA;
        N4 = 2;
        if (p < 128) {              // overlay seg1: 16 groups x 4 cols, N4 = 1
            ovl = true;
            const int g1 = p >> 3, cp1 = (p >> 2) & 1;
            const int b1 = g1 * 64;
            #pragma unroll
            for (int j = 0; j < 2; j++) {
                int k = 4 * h + 2 * j;
                PACK2(wC2[j], w[b1 + k * 4 + cp1],     w[b1 + (k+1) * 4 + cp1]);
                PACK2(wD2[j], w[b1 + k * 4 + cp1 + 2], w[b1 + (k+1) * 4 + cp1 + 2]);
            }
            xoff1 = 4 * g1;
            const int colC = 4 * g1 + cp1;
            colOvl = (h & 1) ? colC + 2 : colC;
        }
    }
    const float bMain = bias[colMain];
    const float bOvl  = ovl ? bias[colOvl] : 0.f;

    // ---- staging: only tid<576 stage; f = tid, r = u (static addresses) ----
    const uint32_t xsAddr = (uint32_t)__cvta_generic_to_shared(Xs);
    const bool stager = tid < 576;
    const uint32_t dstPad = xsAddr + (uint32_t)pad_map(tid < 576 ? tid : 0) * 16;
    const char* srcBase = (const char*)(x + (size_t)row0 * IN_DIM) + (size_t)tid * 16;

    auto stage = [&](int cc) {
        if (!stager) return;
        const uint32_t d0 = dstPad + (uint32_t)(cc & 1) * (XBUF_F4 * 16);
        const char* s0 = srcBase + (size_t)cc * (CHUNK * IN_DIM * 4);
        const int umax = min(CHUNK, nrows - cc * CHUNK);
        #pragma unroll
        for (int u = 0; u < CHUNK; u++)
            if (u < umax) cpa16(d0 + u * (RS4 * 16), s0 + (size_t)u * (IN_DIM * 4));
    };

    // this thread's smem byte offset of its first K-quarter f4 (step = 64B per k4)
    const uint32_t myXBase  = xsAddr + (uint32_t)(xoff + h) * 16;
    const uint32_t myXBase1 = xsAddr + (uint32_t)(xoff1 + h) * 16;

    stage(0);
    asm volatile("cp.async.commit_group;\n");

    for (int c = 0; c < nchunks; c++) {
        asm volatile("cp.async.wait_group 0;\n");
        __syncthreads();   // chunk-c visible; compute(c-1) done before buf reuse
        if (c + 1 < nchunks) {
            stage(c + 1);
            asm volatile("cp.async.commit_group;\n");
        }

        const uint32_t bufOff = (uint32_t)(c & 1) * (XBUF_F4 * 16);
        const int rmax = min(CHUNK, nrows - c * CHUNK);
        float* ob = out + (size_t)(row0 + c * CHUNK) * OUT_DIM;

        #pragma unroll
        for (int r = 0; r < CHUNK; r++) {
            if (r >= rmax) break;
            const uint32_t rowA = bufOff + (uint32_t)r * (RS4 * 16);

            uint64_t sA = 0, sB = 0;
            const uint32_t a = myXBase + rowA;
            if (N4 == 4) {
                #pragma unroll
                for (int k4 = 0; k4 < 4; k4++) {
                    uint64_t u01, u23;
                    LDS_V2B64(u01, u23, a + k4 * 64);
                    FMA2(sA, u01, wA2[2*k4]); FMA2(sA, u23, wA2[2*k4+1]);
                    FMA2(sB, u01, wB2[2*k4]); FMA2(sB, u23, wB2[2*k4+1]);
                }
            } else {
                #pragma unroll
                for (int k4 = 0; k4 < 2; k4++) {
                    uint64_t u01, u23;
                    LDS_V2B64(u01, u23, a + k4 * 64);
                    FMA2(sA, u01, wA2[2*k4]); FMA2(sA, u23, wA2[2*k4+1]);
                    FMA2(sB, u01, wB2[2*k4]); FMA2(sB, u23, wB2[2*k4+1]);
                }
            }

            // 4-lane reduction: xor1 per value, select a/b by lane parity, xor2.
            float av = hsum2(sA), bv = hsum2(sB);
            av += __shfl_xor_sync(0xffffffffu, av, 1);
            bv += __shfl_xor_sync(0xffffffffu, bv, 1);
            float sel = (h & 1) ? bv : av;
            sel += __shfl_xor_sync(0xffffffffu, sel, 2);
            if (h < 2) ob[(size_t)r * OUT_DIM + colMain] = sel + bMain;

            if (ovl) {
                uint64_t sC = 0, sD = 0;
                uint64_t u01, u23;
                LDS_V2B64(u01, u23, myXBase1 + rowA);
                FMA2(sC, u01, wC2[0]); FMA2(sC, u23, wC2[1]);
                FMA2(sD, u01, wD2[0]); FMA2(sD, u23, wD2[1]);
                float cv = hsum2(sC), dv = hsum2(sD);
                cv += __shfl_xor_sync(0xffffffffu, cv, 1);
                dv += __shfl_xor_sync(0xffffffffu, dv, 1);
                float sel1 = (h & 1) ? dv : cv;
                sel1 += __shfl_xor_sync(0xffffffffu, sel1, 2);
                if (h < 2) ob[(size_t)r * OUT_DIM + colOvl] = sel1 + bOvl;
            }
        }
    }
}

extern "C" void kernel_launch(void* const* d_in, const int* in_sizes, int n_in,
                              void* d_out, int out_size)
{
    const float* x    = (const float*)d_in[0];
    const float* wflt = (const float*)d_in[1];
    const float* bias = (const float*)d_in[2];
    float* out        = (float*)d_out;

    cudaFuncSetAttribute(tet_kernel, cudaFuncAttributeMaxDynamicSharedMemorySize, SMEM_BYTES);
    tet_kernel<<<NCTA, THREADS, SMEM_BYTES>>>(x, wflt, bias, out);
}

// round 10
// speedup vs baseline: 1.1342x; 1.1342x over previous
#include <cuda_runtime.h>
#include <cstdint>

#define THREADS 576
#define IN_DIM  2304
#define OUT_DIM 576
#define BATCH   16384
#define RS4     688                 // padded row stride in float4
#define CHUNK   8                   // rows per chunk
#define NCTA    148
#define XBUF_F4 (CHUNK * RS4)       // 5504 float4 per buffer
#define SMEM_BYTES (2 * XBUF_F4 * 16)   // 176128

// Padded smem row layout (float4 indices within one x row):
//   seg1: 16 groups, stride 5  -> [0, 80)
//   seg2: 32 groups, stride 10 -> [80, 400)
//   seg3: 16 groups, stride 18 -> [400, 688)
__device__ __forceinline__ int pad_map(int f) {
    if (f < 64)  return f + (f >> 2);
    if (f < 320) return 80 + (f - 64) + (((f - 64) >> 3) << 1);
    return 400 + (f - 320) + (((f - 320) >> 4) << 1);
}

__device__ __forceinline__ void cpa16(uint32_t daddr, const void* src) {
    asm volatile("cp.async.cg.shared.global [%0], [%1], 16;\n" :: "r"(daddr), "l"(src));
}

// packed f32x2 helpers
#define FMA2(acc, a, b) \
    asm("fma.rn.f32x2 %0, %1, %2, %0;" : "+l"(acc) : "l"(a), "l"(b))
#define PACK2(p, lo, hi) \
    asm("mov.b64 %0, {%1, %2};" : "=l"(p) : "f"(lo), "f"(hi))
#define LDS_V2B64(lo, hi, addr) \
    asm("ld.shared.v2.b64 {%0, %1}, [%2];" : "=l"(lo), "=l"(hi) : "r"(addr))

__device__ __forceinline__ float hsum2(uint64_t p) {
    float lo, hi;
    asm("mov.b64 {%0, %1}, %2;" : "=f"(lo), "=f"(hi) : "l"(p));
    return lo + hi;
}

// Four rows x two columns over this thread's K-half, packed f32x2 math.
// Per k4: 4 LDS.128 (as v2.b64) + 16 FFMA2 (== 64 scalar MACs).
#define DOTPAIR4(N4)                                                         \
    {                                                                        \
        _Pragma("unroll")                                                    \
        for (int k4 = 0; k4 < (N4); k4++) {                                  \
            uint64_t u01, u23, v01, v23, s01, s23, t01, t23;                 \
            LDS_V2B64(u01, u23, a0 + k4 * 32);                               \
            LDS_V2B64(v01, v23, a1 + k4 * 32);                               \
            LDS_V2B64(s01, s23, a2 + k4 * 32);                               \
            LDS_V2B64(t01, t23, a3 + k4 * 32);                               \
            FMA2(sA0, u01, wA2[2*k4]); FMA2(sA0, u23, wA2[2*k4+1]);          \
            FMA2(sB0, u01, wB2[2*k4]); FMA2(sB0, u23, wB2[2*k4+1]);          \
            FMA2(sA1, v01, wA2[2*k4]); FMA2(sA1, v23, wA2[2*k4+1]);          \
            FMA2(sB1, v01, wB2[2*k4]); FMA2(sB1, v23, wB2[2*k4+1]);          \
            FMA2(sA2, s01, wA2[2*k4]); FMA2(sA2, s23, wA2[2*k4+1]);          \
            FMA2(sB2, s01, wB2[2*k4]); FMA2(sB2, s23, wB2[2*k4+1]);          \
            FMA2(sA3, t01, wA2[2*k4]); FMA2(sA3, t23, wA2[2*k4+1]);          \
            FMA2(sB3, t01, wB2[2*k4]); FMA2(sB3, t23, wB2[2*k4+1]);          \
        }                                                                    \
    }

extern "C" __global__ void __launch_bounds__(THREADS, 1)
tet_kernel(const float* __restrict__ x, const float* __restrict__ w,
           const float* __restrict__ bias, float* __restrict__ out)
{
    extern __shared__ __align__(16) float4 Xs[];          // [2][CHUNK][RS4]

    const int tid = threadIdx.x;
    const int bid = blockIdx.x;

    // row partition: 16384 = 148*110 + 104
    const int row0  = bid * 110 + (bid < 104 ? bid : 104);
    const int nrows = 110 + (bid < 104 ? 1 : 0);
    const int nchunks = (nrows + CHUNK - 1) / CHUNK;      // 14

    const int h = tid & 1;          // K-half parity (partner = tid^1)

    // ---- role setup: tid<256 seg3 | tid<512 seg2 | else seg1 ----
    uint64_t wA2[16], wB2[16];
    int xoff, myCol;
    if (tid < 256) {
        const int p = tid >> 1, g3 = p >> 3, cp3 = p & 7;
        const int base = 9216 + g3 * 1024;
        #pragma unroll
        for (int k4 = 0; k4 < 8; k4++)
            #pragma unroll
            for (int j = 0; j < 2; j++) {
                int k = 8 * k4 + 4 * h + 2 * j;
                PACK2(wA2[2*k4+j], w[base + k * 16 + cp3],     w[base + (k+1) * 16 + cp3]);
                PACK2(wB2[2*k4+j], w[base + k * 16 + cp3 + 8], w[base + (k+1) * 16 + cp3 + 8]);
            }
        xoff = 400 + 18 * g3;
        const int colA = 320 + g3 * 16 + cp3;
        myCol = h ? colA + 8 : colA;
    } else if (tid < 512) {
        const int p = (tid - 256) >> 1, g2 = p >> 2, cp2 = p & 3;
        const int base = 1024 + g2 * 256;
        #pragma unroll
        for (int k4 = 0; k4 < 4; k4++)
            #pragma unroll
            for (int j = 0; j < 2; j++) {
                int k = 8 * k4 + 4 * h + 2 * j;
                PACK2(wA2[2*k4+j], w[base + k * 8 + cp2],     w[base + (k+1) * 8 + cp2]);
                PACK2(wB2[2*k4+j], w[base + k * 8 + cp2 + 4], w[base + (k+1) * 8 + cp2 + 4]);
            }
        xoff = 80 + 10 * g2;
        const int colA = 64 + g2 * 8 + cp2;
        myCol = h ? colA + 4 : colA;
    } else {
        const int p = (tid - 512) >> 1, g1 = p >> 1, cp1 = p & 1;
        const int base = g1 * 64;
        #pragma unroll
        for (int k4 = 0; k4 < 2; k4++)
            #pragma unroll
            for (int j = 0; j < 2; j++) {
                int k = 8 * k4 + 4 * h + 2 * j;
                PACK2(wA2[2*k4+j], w[base + k * 4 + cp1],     w[base + (k+1) * 4 + cp1]);
                PACK2(wB2[2*k4+j], w[base + k * 4 + cp1 + 2], w[base + (k+1) * 4 + cp1 + 2]);
            }
        xoff = 5 * g1;
        const int colA = g1 * 4 + cp1;
        myCol = h ? colA + 2 : colA;
    }
    const float myBias = bias[myCol];

    // ---- staging: f = tid (static addresses), r = u ----
    const uint32_t xsAddr = (uint32_t)__cvta_generic_to_shared(Xs);
    const uint32_t dstPad = xsAddr + (uint32_t)pad_map(tid) * 16;
    const char* srcBase = (const char*)(x + (size_t)row0 * IN_DIM) + (size_t)tid * 16;

    auto stage = [&](int cc) {
        const uint32_t d0 = dstPad + (uint32_t)(cc & 1) * (XBUF_F4 * 16);
        const char* s0 = srcBase + (size_t)cc * (CHUNK * IN_DIM * 4);
        const int umax = min(CHUNK, nrows - cc * CHUNK);
        #pragma unroll
        for (int u = 0; u < CHUNK; u++)
            if (u < umax) cpa16(d0 + u * (RS4 * 16), s0 + (size_t)u * (IN_DIM * 4));
    };

    // this thread's smem byte offset of its first K-half float4
    const uint32_t myXBase = xsAddr + (uint32_t)(xoff + h) * 16;

    stage(0);
    asm volatile("cp.async.commit_group;\n");

    for (int c = 0; c < nchunks; c++) {
        asm volatile("cp.async.wait_group 0;\n");
        __syncthreads();   // chunk-c visible; compute(c-1) reads done before reuse
        if (c + 1 < nchunks) {
            stage(c + 1);
            asm volatile("cp.async.commit_group;\n");
        }

        const uint32_t bufAddr = myXBase + (uint32_t)(c & 1) * (XBUF_F4 * 16);
        const int rmax = min(CHUNK, nrows - c * CHUNK);
        float* ob = out + (size_t)(row0 + c * CHUNK) * OUT_DIM;

        #pragma unroll
        for (int r = 0; r < CHUNK; r += 4) {
            if (r >= rmax) break;
            const uint32_t a0 = bufAddr + (uint32_t)r * (RS4 * 16);
            const uint32_t a1 = a0 + 1 * (RS4 * 16);   // smem in-bounds; stores guarded
            const uint32_t a2 = a0 + 2 * (RS4 * 16);
            const uint32_t a3 = a0 + 3 * (RS4 * 16);
            uint64_t sA0 = 0, sB0 = 0, sA1 = 0, sB1 = 0;
            uint64_t sA2 = 0, sB2 = 0, sA3 = 0, sB3 = 0;
            if (tid < 256)      DOTPAIR4(8)
            else if (tid < 512) DOTPAIR4(4)
            else                DOTPAIR4(2)

            float fA0 = hsum2(sA0), fB0 = hsum2(sB0);
            float fA1 = hsum2(sA1), fB1 = hsum2(sB1);
            float fA2 = hsum2(sA2), fB2 = hsum2(sB2);
            float fA3 = hsum2(sA3), fB3 = hsum2(sB3);
            // 8 independent shfls -> pipelined in the SMSP
            float gA0 = __shfl_xor_sync(0xffffffffu, fA0, 1);
            float gB0 = __shfl_xor_sync(0xffffffffu, fB0, 1);
            float gA1 = __shfl_xor_sync(0xffffffffu, fA1, 1);
            float gB1 = __shfl_xor_sync(0xffffffffu, fB1, 1);
            float gA2 = __shfl_xor_sync(0xffffffffu, fA2, 1);
            float gB2 = __shfl_xor_sync(0xffffffffu, fB2, 1);
            float gA3 = __shfl_xor_sync(0xffffffffu, fA3, 1);
            float gB3 = __shfl_xor_sync(0xffffffffu, fB3, 1);
            float r0v = (h ? (fB0 + gB0) : (fA0 + gA0)) + myBias;
            float r1v = (h ? (fB1 + gB1) : (fA1 + gA1)) + myBias;
            float r2v = (h ? (fB2 + gB2) : (fA2 + gA2)) + myBias;
            float r3v = (h ? (fB3 + gB3) : (fA3 + gA3)) + myBias;

            ob[(size_t)r * OUT_DIM + myCol] = r0v;
            if (r + 1 < rmax) ob[(size_t)(r + 1) * OUT_DIM + myCol] = r1v;
            if (r + 2 < rmax) ob[(size_t)(r + 2) * OUT_DIM + myCol] = r2v;
            if (r + 3 < rmax) ob[(size_t)(r + 3) * OUT_DIM + myCol] = r3v;
        }
    }
}

extern "C" void kernel_launch(void* const* d_in, const int* in_sizes, int n_in,
                              void* d_out, int out_size)
{
    const float* x    = (const float*)d_in[0];
    const float* wflt = (const float*)d_in[1];
    const float* bias = (const float*)d_in[2];
    float* out        = (float*)d_out;

    cudaFuncSetAttribute(tet_kernel, cudaFuncAttributeMaxDynamicSharedMemorySize, SMEM_BYTES);
    tet_kernel<<<NCTA, THREADS, SMEM_BYTES>>>(x, wflt, bias, out);
}

// round 11
// speedup vs baseline: 1.1397x; 1.0049x over previous
#include <cuda_runtime.h>
#include <cstdint>

#define THREADS 576
#define IN_DIM  2304
#define OUT_DIM 576
#define BATCH   16384
#define RS4     768                 // padded row stride in float4
#define CHUNK   8                   // rows per chunk
#define NCTA    148
#define XBUF_F4 (CHUNK * RS4)       // 6144 float4 per buffer
#define SMEM_BYTES (2 * XBUF_F4 * 16)   // 196608

// Padded smem row layout (float4 indices within one x row):
//   seg1: 16 groups, stride 4  -> [0, 64)     (unpadded; 4 wavefronts = min)
//   seg2: 32 groups, stride 12 -> [64, 448)   (+16 banks/group: banks hit 2x -> 2 wf = min)
//   seg3: 16 groups, stride 20 -> [448, 768)  (+16 banks/group: 1 wavefront)
__device__ __forceinline__ int pad_map(int f) {
    if (f < 64)  return f;
    if (f < 320) return 64 + (f - 64) + (((f - 64) >> 3) << 2);
    return 448 + (f - 320) + (((f - 320) >> 4) << 2);
}

__device__ __forceinline__ void cpa16(uint32_t daddr, const void* src) {
    asm volatile("cp.async.cg.shared.global [%0], [%1], 16;\n" :: "r"(daddr), "l"(src));
}

// packed f32x2 helpers
#define FMA2(acc, a, b) \
    asm("fma.rn.f32x2 %0, %1, %2, %0;" : "+l"(acc) : "l"(a), "l"(b))
#define PACK2(p, lo, hi) \
    asm("mov.b64 %0, {%1, %2};" : "=l"(p) : "f"(lo), "f"(hi))
#define LDS_V2B64(lo, hi, addr) \
    asm("ld.shared.v2.b64 {%0, %1}, [%2];" : "=l"(lo), "=l"(hi) : "r"(addr))

__device__ __forceinline__ float hsum2(uint64_t p) {
    float lo, hi;
    asm("mov.b64 {%0, %1}, %2;" : "=f"(lo), "=f"(hi) : "l"(p));
    return lo + hi;
}

// 4x4 transpose-reduce within a lane quad: lane h ends with full sum of col h.
__device__ __forceinline__ float quad_reduce(float v0, float v1, float v2, float v3, int h) {
    float a = (h & 1) ? v1 : v0;
    float b = (h & 1) ? v0 : v1;
    a += __shfl_xor_sync(0xffffffffu, b, 1);
    float c = (h & 1) ? v3 : v2;
    float d = (h & 1) ? v2 : v3;
    c += __shfl_xor_sync(0xffffffffu, d, 1);
    float e = (h & 2) ? c : a;
    float f = (h & 2) ? a : c;
    e += __shfl_xor_sync(0xffffffffu, f, 2);
    return e;
}

// Two rows x four columns over this thread's K-quarter.
// Per k4: 2 LDS.128 + 16 FFMA2 (= 64 MACs). 1.0 MAC per shared byte.
#define DOTQUAD(NK4, W)                                                      \
    {                                                                        \
        _Pragma("unroll")                                                    \
        for (int k4 = 0; k4 < (NK4); k4++) {                                 \
            uint64_t u01, u23, v01, v23;                                     \
            LDS_V2B64(u01, u23, a0 + k4 * 64);                               \
            LDS_V2B64(v01, v23, a1 + k4 * 64);                               \
            _Pragma("unroll")                                                \
            for (int cc = 0; cc < 4; cc++) {                                 \
                FMA2(acc0[cc], u01, W[cc][2*k4]);                            \
                FMA2(acc0[cc], u23, W[cc][2*k4+1]);                          \
                FMA2(acc1[cc], v01, W[cc][2*k4]);                            \
                FMA2(acc1[cc], v23, W[cc][2*k4+1]);                          \
            }                                                                \
        }                                                                    \
    }

extern "C" __global__ void __launch_bounds__(THREADS, 1)
tet_kernel(const float* __restrict__ x, const float* __restrict__ w,
           const float* __restrict__ bias, float* __restrict__ out)
{
    extern __shared__ __align__(16) float4 Xs[];          // [2][CHUNK][RS4]

    const int tid = threadIdx.x;
    const int bid = blockIdx.x;

    // row partition: 16384 = 148*110 + 104
    const int row0  = bid * 110 + (bid < 104 ? bid : 104);
    const int nrows = 110 + (bid < 104 ? 1 : 0);
    const int nchunks = (nrows + CHUNK - 1) / CHUNK;      // 14

    const int h = tid & 3;          // lane-in-quad = K-quarter index

    // ---- role setup: tid<256 seg3 | tid<512 seg2 | else seg1 ----
    // Lane h owns f4 {4*k4 + h} of its group => floats k = 16*k4 + 4*h + (0..3).
    uint64_t W3[4][8];              // seg3: 4 cols x 16 k
    int xoff, myCol, nk4;
    if (tid < 256) {
        const int g3 = tid >> 4, cq = (tid >> 2) & 3;
        const int base = 9216 + g3 * 1024 + cq * 4;
        #pragma unroll
        for (int cc = 0; cc < 4; cc++)
            #pragma unroll
            for (int k4 = 0; k4 < 4; k4++)
                #pragma unroll
                for (int j = 0; j < 2; j++) {
                    int k = 16 * k4 + 4 * h + 2 * j;
                    PACK2(W3[cc][2*k4+j], w[base + k * 16 + cc], w[base + (k+1) * 16 + cc]);
                }
        xoff = 448 + 20 * g3;
        myCol = 320 + g3 * 16 + cq * 4 + h;
        nk4 = 4;
    } else if (tid < 512) {
        const int p = tid - 256, g2 = p >> 3, cq = (p >> 2) & 1;
        const int base = 1024 + g2 * 256 + cq * 4;
        #pragma unroll
        for (int cc = 0; cc < 4; cc++)
            #pragma unroll
            for (int k4 = 0; k4 < 2; k4++)
                #pragma unroll
                for (int j = 0; j < 2; j++) {
                    int k = 16 * k4 + 4 * h + 2 * j;
                    PACK2(W3[cc][2*k4+j], w[base + k * 8 + cc], w[base + (k+1) * 8 + cc]);
                }
        xoff = 64 + 12 * g2;
        myCol = 64 + g2 * 8 + cq * 4 + h;
        nk4 = 2;
    } else {
        const int p = tid - 512, g1 = p >> 2;
        const int base = g1 * 64;
        #pragma unroll
        for (int cc = 0; cc < 4; cc++)
            #pragma unroll
            for (int j = 0; j < 2; j++) {
                int k = 4 * h + 2 * j;
                PACK2(W3[cc][j], w[base + k * 4 + cc], w[base + (k+1) * 4 + cc]);
            }
        xoff = 4 * g1;
        myCol = g1 * 4 + h;
        nk4 = 1;
    }
    const float myBias = bias[myCol];

    // ---- staging: f = tid (static addresses), r = u ----
    const uint32_t xsAddr = (uint32_t)__cvta_generic_to_shared(Xs);
    const uint32_t dstPad = xsAddr + (uint32_t)pad_map(tid) * 16;
    const char* srcBase = (const char*)(x + (size_t)row0 * IN_DIM) + (size_t)tid * 16;

    auto stage = [&](int cc) {
        const uint32_t d0 = dstPad + (uint32_t)(cc & 1) * (XBUF_F4 * 16);
        const char* s0 = srcBase + (size_t)cc * (CHUNK * IN_DIM * 4);
        const int umax = min(CHUNK, nrows - cc * CHUNK);
        #pragma unroll
        for (int u = 0; u < CHUNK; u++)
            if (u < umax) cpa16(d0 + u * (RS4 * 16), s0 + (size_t)u * (IN_DIM * 4));
    };

    // this thread's smem byte offset of its first K-quarter f4 (step 64B per k4)
    const uint32_t myXBase = xsAddr + (uint32_t)(xoff + h) * 16;

    stage(0);
    asm volatile("cp.async.commit_group;\n");

    for (int c = 0; c < nchunks; c++) {
        asm volatile("cp.async.wait_group 0;\n");
        __syncthreads();   // chunk-c visible; compute(c-1) reads done before reuse
        if (c + 1 < nchunks) {
            stage(c + 1);
            asm volatile("cp.async.commit_group;\n");
        }

        const uint32_t bufAddr = myXBase + (uint32_t)(c & 1) * (XBUF_F4 * 16);
        const int rmax = min(CHUNK, nrows - c * CHUNK);
        float* ob = out + (size_t)(row0 + c * CHUNK) * OUT_DIM;

        #pragma unroll
        for (int r = 0; r < CHUNK; r += 2) {
            if (r >= rmax) break;
            const uint32_t a0 = bufAddr + (uint32_t)r * (RS4 * 16);
            const uint32_t a1 = a0 + (RS4 * 16);   // smem in-bounds; store guarded
            uint64_t acc0[4] = {0, 0, 0, 0};
            uint64_t acc1[4] = {0, 0, 0, 0};
            if (tid < 256)      DOTQUAD(4, W3)
            else if (tid < 512) DOTQUAD(2, W3)
            else                DOTQUAD(1, W3)

            float r0 = quad_reduce(hsum2(acc0[0]), hsum2(acc0[1]),
                                   hsum2(acc0[2]), hsum2(acc0[3]), h);
            float r1 = quad_reduce(hsum2(acc1[0]), hsum2(acc1[1]),
                                   hsum2(acc1[2]), hsum2(acc1[3]), h);
            ob[(size_t)r * OUT_DIM + myCol] = r0 + myBias;
            if (r + 1 < rmax) ob[(size_t)(r + 1) * OUT_DIM + myCol] = r1 + myBias;
        }
    }
}

extern "C" void kernel_launch(void* const* d_in, const int* in_sizes, int n_in,
                              void* d_out, int out_size)
{
    const float* x    = (const float*)d_in[0];
    const float* wflt = (const float*)d_in[1];
    const float* bias = (const float*)d_in[2];
    float* out        = (float*)d_out;

    cudaFuncSetAttribute(tet_kernel, cudaFuncAttributeMaxDynamicSharedMemorySize, SMEM_BYTES);
    tet_kernel<<<NCTA, THREADS, SMEM_BYTES>>>(x, wflt, bias, out);
}

// round 12
// speedup vs baseline: 1.1934x; 1.0471x over previous
#include <cuda_runtime.h>
#include <cstdint>

#define THREADS 576
#define IN_DIM  2304
#define OUT_DIM 576
#define BATCH   16384
#define RS4     768                 // padded row stride in float4
#define CHUNK   8                   // rows per chunk
#define NCTA    148
#define XBUF_F4 (CHUNK * RS4)       // 6144 float4 per buffer
#define SMEM_BYTES (2 * XBUF_F4 * 16)   // 196608

// Padded smem row layout (float4 indices within one x row):
//   seg1: 16 groups, stride 4  -> [0, 64)
//   seg2: 32 groups, stride 12 -> [64, 448)
//   seg3: 16 groups, stride 20 -> [448, 768)
__device__ __forceinline__ int pad_map(int f) {
    if (f < 64)  return f;
    if (f < 320) return 64 + (f - 64) + (((f - 64) >> 3) << 2);
    return 448 + (f - 320) + (((f - 320) >> 4) << 2);
}

__device__ __forceinline__ void cpa16(uint32_t daddr, const void* src) {
    asm volatile("cp.async.cg.shared.global [%0], [%1], 16;\n" :: "r"(daddr), "l"(src));
}

// packed f32x2 helpers
#define FMA2(acc, a, b) \
    asm("fma.rn.f32x2 %0, %1, %2, %0;" : "+l"(acc) : "l"(a), "l"(b))
#define PACK2(p, lo, hi) \
    asm("mov.b64 %0, {%1, %2};" : "=l"(p) : "f"(lo), "f"(hi))
#define LDS_V2B64(lo, hi, addr) \
    asm("ld.shared.v2.b64 {%0, %1}, [%2];" : "=l"(lo), "=l"(hi) : "r"(addr))

__device__ __forceinline__ float hsum2(uint64_t p) {
    float lo, hi;
    asm("mov.b64 {%0, %1}, %2;" : "=f"(lo), "=f"(hi) : "l"(p));
    return lo + hi;
}

// 4x4 transpose-reduce within a lane quad: lane h ends with full sum of col h.
__device__ __forceinline__ float quad_reduce(float v0, float v1, float v2, float v3, int h) {
    float a = (h & 1) ? v1 : v0;
    float b = (h & 1) ? v0 : v1;
    a += __shfl_xor_sync(0xffffffffu, b, 1);
    float c = (h & 1) ? v3 : v2;
    float d = (h & 1) ? v2 : v3;
    c += __shfl_xor_sync(0xffffffffu, d, 1);
    float e = (h & 2) ? c : a;
    float f = (h & 2) ? a : c;
    e += __shfl_xor_sync(0xffffffffu, f, 2);
    return e;
}

// One row x four columns over this thread's K-quarter.
// Per k4: 1 LDS.128 (16B) + 8 FFMA2 (= 16 MACs). 1.0 MAC per shared byte.
#define DOTQUAD1(NK4, W)                                                     \
    {                                                                        \
        _Pragma("unroll")                                                    \
        for (int k4 = 0; k4 < (NK4); k4++) {                                 \
            uint64_t u01, u23;                                               \
            LDS_V2B64(u01, u23, a0 + k4 * 64);                               \
            _Pragma("unroll")                                                \
            for (int cc = 0; cc < 4; cc++) {                                 \
                FMA2(acc[cc], u01, W[cc][2*k4]);                             \
                FMA2(acc[cc], u23, W[cc][2*k4+1]);                           \
            }                                                                \
        }                                                                    \
    }

extern "C" __global__ void __launch_bounds__(THREADS, 1)
tet_kernel(const float* __restrict__ x, const float* __restrict__ w,
           const float* __restrict__ bias, float* __restrict__ out)
{
    extern __shared__ __align__(16) float4 Xs[];          // [2][CHUNK][RS4]

    const int tid = threadIdx.x;
    const int bid = blockIdx.x;

    // row partition: 16384 = 148*110 + 104
    const int row0  = bid * 110 + (bid < 104 ? bid : 104);
    const int nrows = 110 + (bid < 104 ? 1 : 0);
    const int nchunks = (nrows + CHUNK - 1) / CHUNK;      // 14

    const int h = tid & 3;          // lane-in-quad = K-quarter index

    // ---- role setup: tid<256 seg3 | tid<512 seg2 | else seg1 ----
    // Lane h owns f4 {4*k4 + h} of its group => floats k = 16*k4 + 4*h + (0..3).
    uint64_t W3[4][8];              // seg3: 4 cols x 16 k (8 u64 per col)
    int xoff, myCol;
    if (tid < 256) {
        const int g3 = tid >> 4, cq = (tid >> 2) & 3;
        const int base = 9216 + g3 * 1024 + cq * 4;
        #pragma unroll
        for (int cc = 0; cc < 4; cc++)
            #pragma unroll
            for (int k4 = 0; k4 < 4; k4++)
                #pragma unroll
                for (int j = 0; j < 2; j++) {
                    int k = 16 * k4 + 4 * h + 2 * j;
                    PACK2(W3[cc][2*k4+j], w[base + k * 16 + cc], w[base + (k+1) * 16 + cc]);
                }
        xoff = 448 + 20 * g3;
        myCol = 320 + g3 * 16 + cq * 4 + h;
    } else if (tid < 512) {
        const int p = tid - 256, g2 = p >> 3, cq = (p >> 2) & 1;
        const int base = 1024 + g2 * 256 + cq * 4;
        #pragma unroll
        for (int cc = 0; cc < 4; cc++)
            #pragma unroll
            for (int k4 = 0; k4 < 2; k4++)
                #pragma unroll
                for (int j = 0; j < 2; j++) {
                    int k = 16 * k4 + 4 * h + 2 * j;
                    PACK2(W3[cc][2*k4+j], w[base + k * 8 + cc], w[base + (k+1) * 8 + cc]);
                }
        xoff = 64 + 12 * g2;
        myCol = 64 + g2 * 8 + cq * 4 + h;
    } else {
        const int p = tid - 512, g1 = p >> 2;
        const int base = g1 * 64;
        #pragma unroll
        for (int cc = 0; cc < 4; cc++)
            #pragma unroll
            for (int j = 0; j < 2; j++) {
                int k = 4 * h + 2 * j;
                PACK2(W3[cc][j], w[base + k * 4 + cc], w[base + (k+1) * 4 + cc]);
            }
        xoff = 4 * g1;
        myCol = g1 * 4 + h;
    }
    const float myBias = bias[myCol];

    // ---- staging: f = tid (static addresses), r = u ----
    const uint32_t xsAddr = (uint32_t)__cvta_generic_to_shared(Xs);
    const uint32_t dstPad = xsAddr + (uint32_t)pad_map(tid) * 16;
    const char* srcBase = (const char*)(x + (size_t)row0 * IN_DIM) + (size_t)tid * 16;

    auto stage = [&](int cc) {
        const uint32_t d0 = dstPad + (uint32_t)(cc & 1) * (XBUF_F4 * 16);
        const char* s0 = srcBase + (size_t)cc * (CHUNK * IN_DIM * 4);
        const int umax = min(CHUNK, nrows - cc * CHUNK);
        #pragma unroll
        for (int u = 0; u < CHUNK; u++)
            if (u < umax) cpa16(d0 + u * (RS4 * 16), s0 + (size_t)u * (IN_DIM * 4));
    };

    // this thread's smem byte offset of its first K-quarter f4 (step 64B per k4)
    const uint32_t myXBase = xsAddr + (uint32_t)(xoff + h) * 16;

    stage(0);
    asm volatile("cp.async.commit_group;\n");

    for (int c = 0; c < nchunks; c++) {
        asm volatile("cp.async.wait_group 0;\n");
        __syncthreads();   // chunk-c visible; compute(c-1) reads done before reuse
        if (c + 1 < nchunks) {
            stage(c + 1);
            asm volatile("cp.async.commit_group;\n");
        }

        const uint32_t bufAddr = myXBase + (uint32_t)(c & 1) * (XBUF_F4 * 16);
        const int rmax = min(CHUNK, nrows - c * CHUNK);
        float* ob = out + (size_t)(row0 + c * CHUNK) * OUT_DIM;

        #pragma unroll
        for (int r = 0; r < CHUNK; r++) {
            if (r >= rmax) break;
            const uint32_t a0 = bufAddr + (uint32_t)r * (RS4 * 16);
            uint64_t acc[4] = {0, 0, 0, 0};
            if (tid < 256)      DOTQUAD1(4, W3)
            else if (tid < 512) DOTQUAD1(2, W3)
            else                DOTQUAD1(1, W3)

            float rv = quad_reduce(hsum2(acc[0]), hsum2(acc[1]),
                                   hsum2(acc[2]), hsum2(acc[3]), h);
            ob[(size_t)r * OUT_DIM + myCol] = rv + myBias;
        }
    }
}

extern "C" void kernel_launch(void* const* d_in, const int* in_sizes, int n_in,
                              void* d_out, int out_size)
{
    const float* x    = (const float*)d_in[0];
    const float* wflt = (const float*)d_in[1];
    const float* bias = (const float*)d_in[2];
    float* out        = (float*)d_out;

    cudaFuncSetAttribute(tet_kernel, cudaFuncAttributeMaxDynamicSharedMemorySize, SMEM_BYTES);
    tet_kernel<<<NCTA, THREADS, SMEM_BYTES>>>(x, wflt, bias, out);
}

// round 13
// speedup vs baseline: 1.2621x; 1.0575x over previous
#include <cuda_runtime.h>
#include <cstdint>

#define THREADS 576                 // 18 warps: 8 seg3, 8 seg2, 2 seg1
#define IN_DIM  2304
#define OUT_DIM 576
#define BATCH   16384
#define NCTA    148

#define ROWS_B  4                   // rows per warp buffer
#define NBUF    4                   // ring depth per warp
#define WROW_B  640                 // bytes per row per warp (32 f4 data + pads)
#define WBUF_B  (ROWS_B * WROW_B)   // 2560
#define WREG_B  (NBUF * WBUF_B)     // 10240
#define SMEM_BYTES (18 * WREG_B)    // 184320

__device__ __forceinline__ void cpa16(uint32_t daddr, const void* src) {
    asm volatile("cp.async.cg.shared.global [%0], [%1], 16;\n" :: "r"(daddr), "l"(src));
}

// packed f32x2 helpers
#define FMA2(acc, a, b) \
    asm("fma.rn.f32x2 %0, %1, %2, %0;" : "+l"(acc) : "l"(a), "l"(b))
#define PACK2(p, lo, hi) \
    asm("mov.b64 %0, {%1, %2};" : "=l"(p) : "f"(lo), "f"(hi))
#define LDS_V2B64(lo, hi, addr) \
    asm("ld.shared.v2.b64 {%0, %1}, [%2];" : "=l"(lo), "=l"(hi) : "r"(addr))

__device__ __forceinline__ float hsum2(uint64_t p) {
    float lo, hi;
    asm("mov.b64 {%0, %1}, %2;" : "=f"(lo), "=f"(hi) : "l"(p));
    return lo + hi;
}

// Two rows x two columns over this thread's K-half (R8 inner loop).
#define DOTPAIR2(N4)                                                         \
    {                                                                        \
        _Pragma("unroll")                                                    \
        for (int k4 = 0; k4 < (N4); k4++) {                                  \
            uint64_t u01, u23, v01, v23;                                     \
            LDS_V2B64(u01, u23, a0 + k4 * 32);                               \
            LDS_V2B64(v01, v23, a1 + k4 * 32);                               \
            FMA2(sA0, u01, wA2[2*k4]); FMA2(sA0, u23, wA2[2*k4+1]);          \
            FMA2(sB0, u01, wB2[2*k4]); FMA2(sB0, u23, wB2[2*k4+1]);          \
            FMA2(sA1, v01, wA2[2*k4]); FMA2(sA1, v23, wA2[2*k4+1]);          \
            FMA2(sB1, v01, wB2[2*k4]); FMA2(sB1, v23, wB2[2*k4+1]);          \
        }                                                                    \
    }

extern "C" __global__ void __launch_bounds__(THREADS, 1)
tet_kernel(const float* __restrict__ x, const float* __restrict__ w,
           const float* __restrict__ bias, float* __restrict__ out)
{
    extern __shared__ __align__(16) char Xs[];     // [18 warps][NBUF][ROWS_B][640B]

    const int tid  = threadIdx.x;
    const int wid  = tid >> 5;
    const int lane = tid & 31;
    const int bid  = blockIdx.x;
    const int h    = lane & 1;        // K-half parity (partner = lane^1)

    // row partition: 16384 = 148*110 + 104
    const int row0  = bid * 110 + (bid < 104 ? bid : 104);
    const int nrows = 110 + (bid < 104 ? 1 : 0);
    const int nch   = (nrows + ROWS_B - 1) / ROWS_B;   // 28

    // ================= per-warp role =================
    // Every warp owns a contiguous 32-f4 (512B/row) slice of x and a
    // contiguous 32-column slice of out. Private smem row layout (f4):
    //   seg3 (2 groups x 16): grp at 20*grp   (A:0..15, B:20..35)
    //   seg2 (4 groups x 8) : grp at 10*grp
    //   seg1 (8 groups x 4) : grp at 5*grp
    // All give conflict-minimal LDS (1-2 wavefronts per k4 step).
    int tbase, colbase, nk4, grpoff_f4, smem_sf4, myCol;
    uint64_t wA2[16], wB2[16];

    if (wid < 8) {                       // seg3: groups {2wid, 2wid+1}
        tbase   = 320 + 32 * wid;
        colbase = 320 + 32 * wid;
        nk4 = 8;
        const int grp = lane >> 4, cp = (lane >> 1) & 7;
        grpoff_f4 = 20 * grp;
        smem_sf4  = lane + ((lane >> 4) << 2);        // lane + 4*(lane>=16)
        const int wb = 9216 + (2 * wid + grp) * 1024 + cp;
        #pragma unroll
        for (int k4 = 0; k4 < 8; k4++)
            #pragma unroll
            for (int j = 0; j < 2; j++) {
                int k = 8 * k4 + 4 * h + 2 * j;
                PACK2(wA2[2*k4+j], w[wb + k * 16],     w[wb + (k+1) * 16]);
                PACK2(wB2[2*k4+j], w[wb + k * 16 + 8], w[wb + (k+1) * 16 + 8]);
            }
        const int colA = colbase + 16 * grp + cp;
        myCol = h ? colA + 8 : colA;
    } else if (wid < 16) {               // seg2: groups {4w'..4w'+3}
        const int wj = wid - 8;
        tbase   = 64 + 32 * wj;
        colbase = 64 + 32 * wj;
        nk4 = 4;
        const int grp = lane >> 3, cp = (lane >> 1) & 3;
        grpoff_f4 = 10 * grp;
        smem_sf4  = lane + ((lane >> 3) << 1);        // lane + 2*grp
        const int wb = 1024 + (4 * wj + grp) * 256 + cp;
        #pragma unroll
        for (int k4 = 0; k4 < 4; k4++)
            #pragma unroll
            for (int j = 0; j < 2; j++) {
                int k = 8 * k4 + 4 * h + 2 * j;
                PACK2(wA2[2*k4+j], w[wb + k * 8],     w[wb + (k+1) * 8]);
                PACK2(wB2[2*k4+j], w[wb + k * 8 + 4], w[wb + (k+1) * 8 + 4]);
            }
        const int colA = colbase + 8 * grp + cp;
        myCol = h ? colA + 4 : colA;
    } else {                             // seg1: groups {8w''..8w''+7}
        const int wk = wid - 16;
        tbase   = 32 * wk;
        colbase = 32 * wk;
        nk4 = 2;
        const int grp = lane >> 2, cp = (lane >> 1) & 1;
        grpoff_f4 = 5 * grp;
        smem_sf4  = lane + (lane >> 2);               // lane + grp
        const int wb = (8 * wk + grp) * 64 + cp;
        #pragma unroll
        for (int k4 = 0; k4 < 2; k4++)
            #pragma unroll
            for (int j = 0; j < 2; j++) {
                int k = 8 * k4 + 4 * h + 2 * j;
                PACK2(wA2[2*k4+j], w[wb + k * 4],     w[wb + (k+1) * 4]);
                PACK2(wB2[2*k4+j], w[wb + k * 4 + 2], w[wb + (k+1) * 4 + 2]);
            }
        const int colA = colbase + 4 * grp + cp;
        myCol = h ? colA + 2 : colA;
    }
    const float myBias = bias[myCol];

    // ================= private ring setup =================
    const uint32_t wbase = (uint32_t)__cvta_generic_to_shared(Xs) + wid * WREG_B;
    const uint32_t stDst = wbase + (uint32_t)smem_sf4 * 16;          // staging dst (buf 0, row 0)
    const char* stSrc = (const char*)(x + (size_t)row0 * IN_DIM) + (size_t)(tbase + lane) * 16;
    // compute read base for this lane (buf 0, row 0, k4=0)
    const uint32_t rdBase = wbase + (uint32_t)(grpoff_f4 + h) * 16;

    // stage buffer for chunk i (4 rows), warp-private
    auto stage = [&](int i) {
        const uint32_t d0 = stDst + (uint32_t)(i & (NBUF - 1)) * WBUF_B;
        const char* s0 = stSrc + (size_t)i * (ROWS_B * IN_DIM * 4);
        const int umax = nrows - i * ROWS_B;
        #pragma unroll
        for (int r = 0; r < ROWS_B; r++)
            if (r < umax) cpa16(d0 + r * WROW_B, s0 + (size_t)r * (IN_DIM * 4));
    };

    // prologue: 3 buffers in flight
    stage(0);
    asm volatile("cp.async.commit_group;\n");
    if (nch > 1) stage(1);
    asm volatile("cp.async.commit_group;\n");
    if (nch > 2) stage(2);
    asm volatile("cp.async.commit_group;\n");

    for (int i = 0; i < nch; i++) {
        // outstanding groups: {i, i+1, i+2}; drain i only
        asm volatile("cp.async.wait_group 2;\n");
        __syncwarp();                       // all lanes' buffer-i copies done + visible

        if (i + 3 < nch) stage(i + 3);      // buffer (i+3)%4 == (i-1)%4, computed last iter
        asm volatile("cp.async.commit_group;\n");

        const uint32_t bufRd = rdBase + (uint32_t)(i & (NBUF - 1)) * WBUF_B;
        const int rmax = min(ROWS_B, nrows - i * ROWS_B);
        float* ob = out + (size_t)(row0 + i * ROWS_B) * OUT_DIM;

        #pragma unroll
        for (int r = 0; r < ROWS_B; r += 2) {
            if (r >= rmax) break;
            const uint32_t a0 = bufRd + (uint32_t)r * WROW_B;
            const uint32_t a1 = a0 + WROW_B;          // smem in-bounds; store guarded
            uint64_t sA0 = 0, sB0 = 0, sA1 = 0, sB1 = 0;
            if (nk4 == 8)      DOTPAIR2(8)
            else if (nk4 == 4) DOTPAIR2(4)
            else               DOTPAIR2(2)

            float fA0 = hsum2(sA0), fB0 = hsum2(sB0);
            float fA1 = hsum2(sA1), fB1 = hsum2(sB1);
            fA0 += __shfl_xor_sync(0xffffffffu, fA0, 1);
            fB0 += __shfl_xor_sync(0xffffffffu, fB0, 1);
            fA1 += __shfl_xor_sync(0xffffffffu, fA1, 1);
            fB1 += __shfl_xor_sync(0xffffffffu, fB1, 1);
            float r0v = (h ? fB0 : fA0) + myBias;
            float r1v = (h ? fB1 : fA1) + myBias;
            ob[(size_t)r * OUT_DIM + myCol] = r0v;
            if (r + 1 < rmax) ob[(size_t)(r + 1) * OUT_DIM + myCol] = r1v;
        }
        __syncwarp();   // all lanes done reading buffer (i-? ) before it is re-staged next iter
    }
}

extern "C" void kernel_launch(void* const* d_in, const int* in_sizes, int n_in,
                              void* d_out, int out_size)
{
    const float* x    = (const float*)d_in[0];
    const float* wflt = (const float*)d_in[1];
    const float* bias = (const float*)d_in[2];
    float* out        = (float*)d_out;

    cudaFuncSetAttribute(tet_kernel, cudaFuncAttributeMaxDynamicSharedMemorySize, SMEM_BYTES);
    tet_kernel<<<NCTA, THREADS, SMEM_BYTES>>>(x, wflt, bias, out);
}

// round 14
// speedup vs baseline: 1.2660x; 1.0031x over previous
#include <cuda_runtime.h>
#include <cstdint>

#define THREADS 576                 // 18 warps: 8 seg3, 8 seg2, 2 seg1
#define IN_DIM  2304
#define OUT_DIM 576
#define BATCH   16384
#define NCTA    148

#define ROWS_B  8                   // rows per warp buffer
#define NBUF    2                   // ring depth per warp
#define WROW_B  640                 // bytes per row per warp (32 f4 data + pads)
#define WBUF_B  (ROWS_B * WROW_B)   // 5120
#define WREG_B  (NBUF * WBUF_B)     // 10240
#define SMEM_BYTES (18 * WREG_B)    // 184320

__device__ __forceinline__ void cpa16(uint32_t daddr, const void* src) {
    asm volatile("cp.async.cg.shared.global [%0], [%1], 16;\n" :: "r"(daddr), "l"(src));
}

// packed f32x2 helpers
#define FMA2(acc, a, b) \
    asm("fma.rn.f32x2 %0, %1, %2, %0;" : "+l"(acc) : "l"(a), "l"(b))
#define PACK2(p, lo, hi) \
    asm("mov.b64 %0, {%1, %2};" : "=l"(p) : "f"(lo), "f"(hi))
#define LDS_V2B64(lo, hi, addr) \
    asm("ld.shared.v2.b64 {%0, %1}, [%2];" : "=l"(lo), "=l"(hi) : "r"(addr))

__device__ __forceinline__ float hsum2(uint64_t p) {
    float lo, hi;
    asm("mov.b64 {%0, %1}, %2;" : "=f"(lo), "=f"(hi) : "l"(p));
    return lo + hi;
}

// Two rows x two columns over this thread's K-half (R8/R13 inner loop).
#define DOTPAIR2(N4)                                                         \
    {                                                                        \
        _Pragma("unroll")                                                    \
        for (int k4 = 0; k4 < (N4); k4++) {                                  \
            uint64_t u01, u23, v01, v23;                                     \
            LDS_V2B64(u01, u23, a0 + k4 * 32);                               \
            LDS_V2B64(v01, v23, a1 + k4 * 32);                               \
            FMA2(sA0, u01, wA2[2*k4]); FMA2(sA0, u23, wA2[2*k4+1]);          \
            FMA2(sB0, u01, wB2[2*k4]); FMA2(sB0, u23, wB2[2*k4+1]);          \
            FMA2(sA1, v01, wA2[2*k4]); FMA2(sA1, v23, wA2[2*k4+1]);          \
            FMA2(sB1, v01, wB2[2*k4]); FMA2(sB1, v23, wB2[2*k4+1]);          \
        }                                                                    \
    }

extern "C" __global__ void __launch_bounds__(THREADS, 1)
tet_kernel(const float* __restrict__ x, const float* __restrict__ w,
           const float* __restrict__ bias, float* __restrict__ out)
{
    extern __shared__ __align__(16) char Xs[];     // [18 warps][NBUF][ROWS_B][640B]

    const int tid  = threadIdx.x;
    const int wid  = tid >> 5;
    const int lane = tid & 31;
    const int bid  = blockIdx.x;
    const int h    = lane & 1;        // K-half parity (partner = lane^1)

    // row partition: 16384 = 148*110 + 104
    const int row0  = bid * 110 + (bid < 104 ? bid : 104);
    const int nrows = 110 + (bid < 104 ? 1 : 0);
    const int nch   = (nrows + ROWS_B - 1) / ROWS_B;   // 14

    // ================= per-warp role =================
    // Every warp owns a contiguous 32-f4 (512B/row) slice of x and a
    // contiguous 32-column slice of out. Private smem row layout (f4):
    //   seg3 (2 groups x 16): grp at 20*grp
    //   seg2 (4 groups x 8) : grp at 10*grp
    //   seg1 (8 groups x 4) : grp at 5*grp
    int tbase, nk4, grpoff_f4, smem_sf4, myCol;
    uint64_t wA2[16], wB2[16];

    if (wid < 8) {                       // seg3: groups {2wid, 2wid+1}
        tbase = 320 + 32 * wid;
        nk4 = 8;
        const int grp = lane >> 4, cp = (lane >> 1) & 7;
        grpoff_f4 = 20 * grp;
        smem_sf4  = lane + ((lane >> 4) << 2);
        const int wb = 9216 + (2 * wid + grp) * 1024 + cp;
        #pragma unroll
        for (int k4 = 0; k4 < 8; k4++)
            #pragma unroll
            for (int j = 0; j < 2; j++) {
                int k = 8 * k4 + 4 * h + 2 * j;
                PACK2(wA2[2*k4+j], w[wb + k * 16],     w[wb + (k+1) * 16]);
                PACK2(wB2[2*k4+j], w[wb + k * 16 + 8], w[wb + (k+1) * 16 + 8]);
            }
        const int colA = 320 + 32 * wid + 16 * grp + cp;
        myCol = h ? colA + 8 : colA;
    } else if (wid < 16) {               // seg2
        const int wj = wid - 8;
        tbase = 64 + 32 * wj;
        nk4 = 4;
        const int grp = lane >> 3, cp = (lane >> 1) & 3;
        grpoff_f4 = 10 * grp;
        smem_sf4  = lane + ((lane >> 3) << 1);
        const int wb = 1024 + (4 * wj + grp) * 256 + cp;
        #pragma unroll
        for (int k4 = 0; k4 < 4; k4++)
            #pragma unroll
            for (int j = 0; j < 2; j++) {
                int k = 8 * k4 + 4 * h + 2 * j;
                PACK2(wA2[2*k4+j], w[wb + k * 8],     w[wb + (k+1) * 8]);
                PACK2(wB2[2*k4+j], w[wb + k * 8 + 4], w[wb + (k+1) * 8 + 4]);
            }
        const int colA = 64 + 32 * wj + 8 * grp + cp;
        myCol = h ? colA + 4 : colA;
    } else {                             // seg1
        const int wk = wid - 16;
        tbase = 32 * wk;
        nk4 = 2;
        const int grp = lane >> 2, cp = (lane >> 1) & 1;
        grpoff_f4 = 5 * grp;
        smem_sf4  = lane + (lane >> 2);
        const int wb = (8 * wk + grp) * 64 + cp;
        #pragma unroll
        for (int k4 = 0; k4 < 2; k4++)
            #pragma unroll
            for (int j = 0; j < 2; j++) {
                int k = 8 * k4 + 4 * h + 2 * j;
                PACK2(wA2[2*k4+j], w[wb + k * 4],     w[wb + (k+1) * 4]);
                PACK2(wB2[2*k4+j], w[wb + k * 4 + 2], w[wb + (k+1) * 4 + 2]);
            }
        const int colA = 32 * wk + 4 * grp + cp;
        myCol = h ? colA + 2 : colA;
    }
    const float myBias = bias[myCol];

    // ================= private ring setup =================
    const uint32_t wbase = (uint32_t)__cvta_generic_to_shared(Xs) + wid * WREG_B;
    const uint32_t stDst = wbase + (uint32_t)smem_sf4 * 16;
    const char* stSrc = (const char*)(x + (size_t)row0 * IN_DIM) + (size_t)(tbase + lane) * 16;
    const uint32_t rdBase = wbase + (uint32_t)(grpoff_f4 + h) * 16;

    // stage buffer for chunk i (8 rows), warp-private, 8 back-to-back cp.asyncs
    auto stage = [&](int i) {
        const uint32_t d0 = stDst + (uint32_t)(i & (NBUF - 1)) * WBUF_B;
        const char* s0 = stSrc + (size_t)i * (ROWS_B * IN_DIM * 4);
        const int umax = nrows - i * ROWS_B;
        #pragma unroll
        for (int r = 0; r < ROWS_B; r++)
            if (r < umax) cpa16(d0 + r * WROW_B, s0 + (size_t)r * (IN_DIM * 4));
    };

    // prologue: buffer 0 in flight
    stage(0);
    asm volatile("cp.async.commit_group;\n");

    for (int i = 0; i < nch; i++) {
        if (i + 1 < nch) stage(i + 1);      // buf (i+1)%2: chunk i-1's, compute done
        asm volatile("cp.async.commit_group;\n");   // uniform group count
        // outstanding: {i, i+1}; drain i only
        asm volatile("cp.async.wait_group 1;\n");
        __syncwarp();                       // chunk-i data visible warp-wide

        const uint32_t bufRd = rdBase + (uint32_t)(i & (NBUF - 1)) * WBUF_B;
        const int rmax = min(ROWS_B, nrows - i * ROWS_B);
        float* ob = out + (size_t)(row0 + i * ROWS_B) * OUT_DIM;

        #pragma unroll
        for (int r = 0; r < ROWS_B; r += 2) {
            if (r >= rmax) break;
            const uint32_t a0 = bufRd + (uint32_t)r * WROW_B;
            const uint32_t a1 = a0 + WROW_B;          // smem in-bounds; store guarded
            uint64_t sA0 = 0, sB0 = 0, sA1 = 0, sB1 = 0;
            if (nk4 == 8)      DOTPAIR2(8)
            else if (nk4 == 4) DOTPAIR2(4)
            else               DOTPAIR2(2)

            float fA0 = hsum2(sA0), fB0 = hsum2(sB0);
            float fA1 = hsum2(sA1), fB1 = hsum2(sB1);
            fA0 += __shfl_xor_sync(0xffffffffu, fA0, 1);
            fB0 += __shfl_xor_sync(0xffffffffu, fB0, 1);
            fA1 += __shfl_xor_sync(0xffffffffu, fA1, 1);
            fB1 += __shfl_xor_sync(0xffffffffu, fB1, 1);
            float r0v = (h ? fB0 : fA0) + myBias;
            float r1v = (h ? fB1 : fA1) + myBias;
            ob[(size_t)r * OUT_DIM + myCol] = r0v;
            if (r + 1 < rmax) ob[(size_t)(r + 1) * OUT_DIM + myCol] = r1v;
        }
        __syncwarp();   // all lanes done reading buf i before it's re-staged next iter
    }
}

extern "C" void kernel_launch(void* const* d_in, const int* in_sizes, int n_in,
                              void* d_out, int out_size)
{
    const float* x    = (const float*)d_in[0];
    const float* wflt = (const float*)d_in[1];
    const float* bias = (const float*)d_in[2];
    float* out        = (float*)d_out;

    cudaFuncSetAttribute(tet_kernel, cudaFuncAttributeMaxDynamicSharedMemorySize, SMEM_BYTES);
    tet_kernel<<<NCTA, THREADS, SMEM_BYTES>>>(x, wflt, bias, out);
}